// round 4
// baseline (speedup 1.0000x reference)
#include <cuda_runtime.h>
#include <cuda_bf16.h>

// LIF spike scan: x [B=32, T=16, C=128, H=32, W=32] fp32 -> spikes (fp32, same shape).
// Per site: mem = mem*TAU + x_t; s = (mem >= THRESH); mem = (1-s)*mem.
//
// HBM-bound (512 MiB total). R4: balance occupancy × per-warp MLP.
//  - one float4 per thread (coalesced 512B/warp per access)
//  - timesteps processed in groups of 4: 4 streaming loads batched, scan,
//    4 streaming stores. Only ~8 vector values live -> ~40 regs -> ~60% occ,
//    while each warp keeps 4 outstanding LDG.128.
//  - __ldcs/__stcs: zero reuse, L2 evict-first (R3's proven bump).

#define LIF_T      16
#define LIF_THRESH 0.5f
#define LIF_TAU    0.25f
#define LIF_G      4              // timesteps per group

__global__ __launch_bounds__(256) void lif_spike_kernel(
    const float4* __restrict__ x,   // [B, T, CHW/4] viewed as float4
    float4* __restrict__ out,
    int chw4,                        // C*H*W/4 = 32768
    int n_sites)                     // B * chw4
{
    int gid = blockIdx.x * blockDim.x + threadIdx.x;
    if (gid >= n_sites) return;

    int b  = gid / chw4;
    int sp = gid - b * chw4;

    long base = (long)b * (LIF_T * (long)chw4) + sp;

    float4 mem = make_float4(0.f, 0.f, 0.f, 0.f);

#pragma unroll
    for (int g = 0; g < LIF_T / LIF_G; g++) {
        float4 v[LIF_G];

        // batch this group's loads (4 outstanding LDG.128 per warp)
#pragma unroll
        for (int t = 0; t < LIF_G; t++) {
            v[t] = __ldcs(&x[base + (long)(g * LIF_G + t) * chw4]);
        }

        // sequential LIF scan, 4 lanes in parallel
#pragma unroll
        for (int t = 0; t < LIF_G; t++) {
            mem.x = fmaf(mem.x, LIF_TAU, v[t].x);
            mem.y = fmaf(mem.y, LIF_TAU, v[t].y);
            mem.z = fmaf(mem.z, LIF_TAU, v[t].z);
            mem.w = fmaf(mem.w, LIF_TAU, v[t].w);

            float sx = (mem.x >= LIF_THRESH) ? 1.f : 0.f;
            float sy = (mem.y >= LIF_THRESH) ? 1.f : 0.f;
            float sz = (mem.z >= LIF_THRESH) ? 1.f : 0.f;
            float sw = (mem.w >= LIF_THRESH) ? 1.f : 0.f;

            mem.x = (sx != 0.f) ? 0.f : mem.x;
            mem.y = (sy != 0.f) ? 0.f : mem.y;
            mem.z = (sz != 0.f) ? 0.f : mem.z;
            mem.w = (sw != 0.f) ? 0.f : mem.w;

            v[t] = make_float4(sx, sy, sz, sw);
        }

        // batch this group's stores (streaming, evict-first)
#pragma unroll
        for (int t = 0; t < LIF_G; t++) {
            __stcs(&out[base + (long)(g * LIF_G + t) * chw4], v[t]);
        }
    }
}

extern "C" void kernel_launch(void* const* d_in, const int* in_sizes, int n_in,
                              void* d_out, int out_size)
{
    const float* x = (const float*)d_in[0];
    float* out = (float*)d_out;

    // x: [32, 16, 128, 32, 32] => B=32, T=16, CHW=131072
    const int chw  = 128 * 32 * 32;                 // 131072
    const int chw4 = chw / 4;                       // 32768
    const int B    = in_sizes[0] / (LIF_T * chw);   // 32
    const int n_sites = B * chw4;                   // 1,048,576

    const int threads = 256;
    const int blocks = (n_sites + threads - 1) / threads;

    lif_spike_kernel<<<blocks, threads>>>(
        (const float4*)x, (float4*)out, chw4, n_sites);
}

// round 5
// speedup vs baseline: 1.0074x; 1.0074x over previous
#include <cuda_runtime.h>
#include <cuda_bf16.h>

// LIF spike scan: x [B=32, T=16, C=128, H=32, W=32] fp32 -> spikes (fp32, same shape).
// Per site: mem = mem*TAU + x_t; s = (mem >= THRESH); mem = (1-s)*mem.
//
// HBM/LTS-bound: three structurally different variants all saturate at
// ~6.4 TB/s (path-independent LTS cap at DVFS'd clock). R5 keeps the fastest
// structure (R3: 16 streaming loads batched, scan, 16 streaming stores) and
// strips issue-side overhead: compile-time shapes (division -> shift),
// pure 32-bit indexing, no bounds guard (grid divides exactly).

#define LIF_T      16
#define LIF_THRESH 0.5f
#define LIF_TAU    0.25f
#define LIF_CHW4   32768           // C*H*W/4 = 128*32*32/4 (compile-time)

__global__ __launch_bounds__(256) void lif_spike_kernel(
    const float4* __restrict__ x,   // [B, T, CHW/4] viewed as float4
    float4* __restrict__ out)
{
    // gid in [0, B*CHW4) = [0, 1048576); all indices fit 32-bit.
    unsigned gid = blockIdx.x * blockDim.x + threadIdx.x;
    unsigned b   = gid >> 15;              // gid / LIF_CHW4
    unsigned sp  = gid & (LIF_CHW4 - 1);   // gid % LIF_CHW4

    // float4 offset of (b, t=0, sp); max = 32*16*32768 = 2^24, fits 32-bit.
    unsigned base = b * (LIF_T * LIF_CHW4) + sp;

    // All 16 time-step loads are independent; streaming (evict-first).
    float4 v[LIF_T];
#pragma unroll
    for (int t = 0; t < LIF_T; t++) {
        v[t] = __ldcs(&x[base + t * LIF_CHW4]);
    }

    // Sequential LIF scan in registers, 4 lanes in parallel.
    float4 mem = make_float4(0.f, 0.f, 0.f, 0.f);
#pragma unroll
    for (int t = 0; t < LIF_T; t++) {
        mem.x = fmaf(mem.x, LIF_TAU, v[t].x);
        mem.y = fmaf(mem.y, LIF_TAU, v[t].y);
        mem.z = fmaf(mem.z, LIF_TAU, v[t].z);
        mem.w = fmaf(mem.w, LIF_TAU, v[t].w);

        float sx = (mem.x >= LIF_THRESH) ? 1.f : 0.f;
        float sy = (mem.y >= LIF_THRESH) ? 1.f : 0.f;
        float sz = (mem.z >= LIF_THRESH) ? 1.f : 0.f;
        float sw = (mem.w >= LIF_THRESH) ? 1.f : 0.f;

        // hard reset
        mem.x = (sx != 0.f) ? 0.f : mem.x;
        mem.y = (sy != 0.f) ? 0.f : mem.y;
        mem.z = (sz != 0.f) ? 0.f : mem.z;
        mem.w = (sw != 0.f) ? 0.f : mem.w;

        v[t] = make_float4(sx, sy, sz, sw);   // reuse v[] as output buffer
    }

#pragma unroll
    for (int t = 0; t < LIF_T; t++) {
        __stcs(&out[base + t * LIF_CHW4], v[t]);
    }
}

extern "C" void kernel_launch(void* const* d_in, const int* in_sizes, int n_in,
                              void* d_out, int out_size)
{
    const float* x = (const float*)d_in[0];
    float* out = (float*)d_out;

    // x: [32, 16, 128, 32, 32]; n_sites = 32 * 32768 = 1,048,576 float4 sites.
    const int chw  = 128 * 32 * 32;
    const int B    = in_sizes[0] / (LIF_T * chw);   // 32
    const int n_sites = B * LIF_CHW4;               // 1,048,576

    const int threads = 256;
    const int blocks = n_sites / threads;           // 4096, exact

    lif_spike_kernel<<<blocks, threads>>>((const float4*)x, (float4*)out);
}